// round 8
// baseline (speedup 1.0000x reference)
#include <cuda_runtime.h>
#include <stdint.h>
#include <math.h>

// Problem constants (fixed by dataset)
#define MAXN     100000
#define FIN      128
#define HID      64
#define NBW      ((MAXN + 31) / 32)   // 3125 bitmap words = 12.5 KB
#define MAXSLOTS 16384                // |V1| bound (actual ~2.1k)
#define MAXL2    65536                // layer-2 edge bound (actual ~2k)
#define CBLK     16                   // slots per compute chunk

// ---------------- static device scratch (zero at entry; tail re-zeroes) -----
__device__ int      d_deg[MAXN];
__device__ unsigned d_isout_bits[NBW];
__device__ unsigned d_need_bits[NBW];
__device__ int      d_slot[MAXN];               // node -> slot (valid iff need bit)
__device__ int      d_slotnode[MAXSLOTS];       // slot -> node
__device__ __align__(16) float d_xagg[(size_t)MAXSLOTS * FIN]; // rows zeroed lazily
__device__ float    d_tval[MAXSLOTS];           // relu(h1)@W2 per slot
__device__ float    d_sdinv[MAXSLOTS];          // dinv per slot
__device__ int2     d_l2[MAXL2];                // edges into output nodes
__device__ int      d_nslots;
__device__ int      d_nl2;

__device__ __forceinline__ void red_add_v4(float* addr, float a, float b, float c, float d) {
    asm volatile("red.global.add.v4.f32 [%0], {%1,%2,%3,%4};"
                 :: "l"(addr), "f"(a), "f"(b), "f"(c), "f"(d) : "memory");
}
__device__ __forceinline__ int test_bit(const unsigned* bits, int i) {
    return (bits[i >> 5] >> (i & 31)) & 1u;
}
__device__ __forceinline__ void zero_row(int s) {
    float4* row = (float4*)&d_xagg[(size_t)s * FIN];
    #pragma unroll
    for (int k = 0; k < FIN / 4; k++) row[k] = make_float4(0.f, 0.f, 0.f, 0.f);
}

// ---------------------------------------------------------------------------
// Mark output nodes (last of each graph, batch sorted); init out[] with bias.
__global__ void k_mark(const int* __restrict__ batch, int N,
                       float* __restrict__ out, const float* __restrict__ b2, int G) {
    int i = blockIdx.x * blockDim.x + threadIdx.x;
    if (i < G) out[i] = b2[0];
    if (i >= N) return;
    bool last = (i == N - 1) || (batch[i] != batch[i + 1]);
    if (last) {
        atomicOr(&d_isout_bits[i >> 5], 1u << (i & 31));
        atomicOr(&d_need_bits[i >> 5], 1u << (i & 31));
        int s = atomicAdd(&d_nslots, 1);
        if (s < MAXSLOTS) { d_slot[i] = s; d_slotnode[s] = i; zero_row(s); }
    }
}

// pass1: deg histogram (RED) + collect layer-2 edges + extend V1 slot set.
__device__ __forceinline__ void pass1_hit(int sj, int dj) {
    int p = atomicAdd(&d_nl2, 1);
    if (p < MAXL2) d_l2[p] = make_int2(sj, dj);
    unsigned bit = 1u << (sj & 31);
    unsigned old = atomicOr(&d_need_bits[sj >> 5], bit);
    if (!(old & bit)) {                              // winner assigns + zeroes
        int s = atomicAdd(&d_nslots, 1);
        if (s < MAXSLOTS) { d_slot[sj] = s; d_slotnode[s] = sj; zero_row(s); }
    }
}

__global__ void k_pass1_v4(const int* __restrict__ src, const int4* __restrict__ dst4, int E4) {
    int j = blockIdx.x * blockDim.x + threadIdx.x;
    if (j >= E4) return;
    int4 d = __ldg(&dst4[j]);
    atomicAdd(&d_deg[d.x], 1);
    atomicAdd(&d_deg[d.y], 1);
    atomicAdd(&d_deg[d.z], 1);
    atomicAdd(&d_deg[d.w], 1);
    if (test_bit(d_isout_bits, d.x)) pass1_hit(__ldg(&src[4 * j + 0]), d.x);
    if (test_bit(d_isout_bits, d.y)) pass1_hit(__ldg(&src[4 * j + 1]), d.y);
    if (test_bit(d_isout_bits, d.z)) pass1_hit(__ldg(&src[4 * j + 2]), d.z);
    if (test_bit(d_isout_bits, d.w)) pass1_hit(__ldg(&src[4 * j + 3]), d.w);
}
__global__ void k_pass1_s(const int* __restrict__ src, const int* __restrict__ dst, int E) {
    int i = blockIdx.x * blockDim.x + threadIdx.x;
    if (i >= E) return;
    int dj = __ldg(&dst[i]);
    atomicAdd(&d_deg[dj], 1);
    if (test_bit(d_isout_bits, dj)) pass1_hit(__ldg(&src[i]), dj);
}

// scatter: edges into V1 nodes -> warp-cooperative red.v4 of x[src]*dinv[src]
__global__ void k_scatter(const int* __restrict__ src, const int* __restrict__ dst,
                          const float4* __restrict__ x4, int E) {
    int idx  = blockIdx.x * blockDim.x + threadIdx.x;
    int lane = threadIdx.x & 31;
    int s = 0, d = 0, sl = 0, pred = 0;
    float w = 0.f;
    if (idx < E) {
        d = __ldg(&dst[idx]);
        pred = test_bit(d_need_bits, d);             // 12.5 KB bitmap: L1 hit
        if (pred) {
            s  = __ldg(&src[idx]);
            sl = d_slot[d];
            w  = rsqrtf((float)(__ldg(&d_deg[s]) + 1));
        }
    }
    unsigned m = __ballot_sync(0xffffffffu, pred);
    while (m) {
        int b = __ffs(m) - 1;
        m &= m - 1;
        int   bs  = __shfl_sync(0xffffffffu, s,  b);
        int   bsl = __shfl_sync(0xffffffffu, sl, b);
        float bw  = __shfl_sync(0xffffffffu, w,  b);
        float4 xv = __ldg(&x4[(size_t)bs * (FIN / 4) + lane]);
        red_add_v4(&d_xagg[(size_t)bsl * FIN + lane * 4],
                   xv.x * bw, xv.y * bw, xv.z * bw, xv.w * bw);
    }
}

// compute: persistent blocks, W1 in smem ONCE per block, 16 slots per chunk.
// y[si] = xagg[si]*dv + x[v]*dv^2 ; h = relu(y@W1+b1) ; tval = h@W2 (+ self term)
__global__ void __launch_bounds__(256) k_compute(const float* __restrict__ x,
                          const float* __restrict__ W1,
                          const float* __restrict__ b1,
                          const float* __restrict__ W2,
                          const int*   __restrict__ batch,
                          float* __restrict__ out) {
    __shared__ float W1s[FIN * HID];                 // 32 KB
    __shared__ __align__(16) float ysh[CBLK][FIN];   // 8 KB
    __shared__ float red[CBLK * HID];                // 4 KB
    __shared__ float b1s[HID], W2s[HID];
    __shared__ int   s_v[CBLK];
    __shared__ float s_dv[CBLK];

    int tid = threadIdx.x;
    // stage weights once
    {
        const float4* w4 = (const float4*)W1;
        float4* s4 = (float4*)W1s;
        for (int i = tid; i < FIN * HID / 4; i += 256) s4[i] = __ldg(&w4[i]);
        if (tid < HID) { b1s[tid] = __ldg(&b1[tid]); W2s[tid] = __ldg(&W2[tid]); }
    }
    __syncthreads();

    int ns = d_nslots; if (ns > MAXSLOTS) ns = MAXSLOTS;
    int t   = tid & 63;       // hidden index
    int sub = tid >> 6;       // 0..3 slot subgroup

    for (int base = blockIdx.x * CBLK; base < ns; base += gridDim.x * CBLK) {
        int nc = ns - base; if (nc > CBLK) nc = CBLK;
        if (tid < nc) {
            int v = d_slotnode[base + tid];
            float dv = rsqrtf((float)(d_deg[v] + 1));
            s_v[tid] = v;
            s_dv[tid] = dv;
            d_sdinv[base + tid] = dv;
        }
        __syncthreads();
        // stage y rows (coalesced per row)
        for (int idx = tid; idx < nc * FIN; idx += 256) {
            int si = idx >> 7, k = idx & (FIN - 1);
            int v = s_v[si];
            float dv = s_dv[si];
            ysh[si][k] = d_xagg[(size_t)(base + si) * FIN + k] * dv
                       + __ldg(&x[(size_t)v * FIN + k]) * dv * dv;
        }
        __syncthreads();
        // small GEMM: thread computes (slot sub+4q, hid t) for q=0..3
        float a0 = b1s[t], a1 = a0, a2 = a0, a3 = a0;
        const float4* y0 = (const float4*)ysh[sub];
        const float4* y1 = (const float4*)ysh[sub + 4];
        const float4* y2 = (const float4*)ysh[sub + 8];
        const float4* y3 = (const float4*)ysh[sub + 12];
        #pragma unroll
        for (int k4 = 0; k4 < FIN / 4; k4++) {
            float w0 = W1s[(4 * k4 + 0) * HID + t];
            float w1 = W1s[(4 * k4 + 1) * HID + t];
            float w2 = W1s[(4 * k4 + 2) * HID + t];
            float w3 = W1s[(4 * k4 + 3) * HID + t];
            float4 v0 = y0[k4], v1 = y1[k4], v2 = y2[k4], v3 = y3[k4];
            a0 = fmaf(v0.x, w0, a0); a0 = fmaf(v0.y, w1, a0);
            a0 = fmaf(v0.z, w2, a0); a0 = fmaf(v0.w, w3, a0);
            a1 = fmaf(v1.x, w0, a1); a1 = fmaf(v1.y, w1, a1);
            a1 = fmaf(v1.z, w2, a1); a1 = fmaf(v1.w, w3, a1);
            a2 = fmaf(v2.x, w0, a2); a2 = fmaf(v2.y, w1, a2);
            a2 = fmaf(v2.z, w2, a2); a2 = fmaf(v2.w, w3, a2);
            a3 = fmaf(v3.x, w0, a3); a3 = fmaf(v3.y, w1, a3);
            a3 = fmaf(v3.z, w2, a3); a3 = fmaf(v3.w, w3, a3);
        }
        float wt = W2s[t];
        red[(sub +  0) * HID + t] = fmaxf(a0, 0.f) * wt;
        red[(sub +  4) * HID + t] = fmaxf(a1, 0.f) * wt;
        red[(sub +  8) * HID + t] = fmaxf(a2, 0.f) * wt;
        red[(sub + 12) * HID + t] = fmaxf(a3, 0.f) * wt;
        __syncthreads();
        // warp w reduces slots 2w, 2w+1
        int wrp = tid >> 5, lane = tid & 31;
        #pragma unroll
        for (int r = 0; r < 2; r++) {
            int si = 2 * wrp + r;
            float p = red[si * HID + lane] + red[si * HID + lane + 32];
            #pragma unroll
            for (int o = 16; o > 0; o >>= 1)
                p += __shfl_down_sync(0xffffffffu, p, o);
            if (lane == 0 && si < nc) {
                d_tval[base + si] = p;
                int v = s_v[si];
                if (test_bit(d_isout_bits, v)) {     // layer-2 self-loop term
                    float dv = s_dv[si];
                    atomicAdd(&out[batch[v]], p * dv * dv);
                }
            }
        }
        __syncthreads();
    }
}

// block 0: layer-2 edge reduce; all blocks: zero scratch for the next call
__global__ void k_final(const int* __restrict__ batch, float* __restrict__ out) {
    int i = blockIdx.x * blockDim.x + threadIdx.x;
    if (blockIdx.x == 0) {
        int n1 = d_nl2; if (n1 > MAXL2) n1 = MAXL2;
        for (int k = threadIdx.x; k < n1; k += blockDim.x) {
            int2 e = d_l2[k];
            int ss = d_slot[e.x];
            int sd = d_slot[e.y];
            atomicAdd(&out[batch[e.y]], d_tval[ss] * d_sdinv[ss] * d_sdinv[sd]);
        }
        __syncthreads();
        if (threadIdx.x == 0) { d_nl2 = 0; d_nslots = 0; }
    }
    if (i < MAXN) d_deg[i] = 0;
    if (i < NBW) { d_isout_bits[i] = 0u; d_need_bits[i] = 0u; }
}

// ---------------------------------------------------------------------------
extern "C" void kernel_launch(void* const* d_in, const int* in_sizes, int n_in,
                              void* d_out, int out_size) {
    const float* x     = (const float*)d_in[0];
    const int*   ei    = (const int*)  d_in[1];
    const int*   batch = (const int*)  d_in[2];
    const float* W1    = (const float*)d_in[3];
    const float* b1    = (const float*)d_in[4];
    const float* W2    = (const float*)d_in[5];
    const float* b2    = (const float*)d_in[6];
    float* out = (float*)d_out;

    const int N = in_sizes[2];
    const int E = in_sizes[1] / 2;
    const int G = out_size;

    const int* src = ei;
    const int* dst = ei + E;

    int gN = (N + 255) / 256;

    k_mark<<<gN, 256>>>(batch, N, out, b2, G);

    bool vec_ok = ((E & 3) == 0) &&
                  ((((uintptr_t)src) & 15) == 0) && ((((uintptr_t)dst) & 15) == 0);
    if (vec_ok) {
        int E4 = E / 4;
        k_pass1_v4<<<(E4 + 255) / 256, 256>>>(src, (const int4*)dst, E4);
    } else {
        k_pass1_s<<<(E + 255) / 256, 256>>>(src, dst, E);
    }

    k_scatter<<<(E + 255) / 256, 256>>>(src, dst, (const float4*)x, E);
    k_compute<<<148, 256>>>(x, W1, b1, W2, batch, out);
    k_final  <<<gN, 256>>>(batch, out);
}

// round 9
// speedup vs baseline: 1.0385x; 1.0385x over previous
#include <cuda_runtime.h>
#include <stdint.h>
#include <math.h>

// Problem constants (fixed by dataset)
#define MAXN     100000
#define MAXE     3200000
#define FIN      128
#define HID      64
#define NBW      ((MAXN + 31) / 32)   // 12.5 KB bitmaps
#define MAXSLOTS 16384                // |V1| bound (actual ~2.1k)
#define MAXL2    65536                // layer-2 edge bound (actual ~2k)
#define MSHIFT   41                   // magic-division shift

// ---------------- static device scratch ------------------------------------
// Zero-initialized at load; k_final re-zeroes everything it dirties.
__device__ int      d_deg[MAXN];
__device__ float    d_dinv[MAXN];
__device__ unsigned d_isout_bits[NBW];
__device__ unsigned d_need_bits[NBW];
__device__ int      d_slot[MAXN];
__device__ int      d_slotnode[MAXSLOTS];
__device__ __align__(16) float d_xagg[(size_t)MAXSLOTS * FIN];
__device__ float    d_tval[MAXSLOTS];
__device__ int2     d_l2[MAXL2];
__device__ int      d_outnodes[MAXSLOTS];
__device__ int      d_nslots;
__device__ int      d_nl2;
__device__ int      d_nout;
__device__ int      d_formula_ok = 1;   // batch matches (i*G)//N ?

__device__ __forceinline__ void red_add_v4(float* addr, float a, float b, float c, float d) {
    asm volatile("red.global.add.v4.f32 [%0], {%1,%2,%3,%4};"
                 :: "l"(addr), "f"(a), "f"(b), "f"(c), "f"(d) : "memory");
}
__device__ __forceinline__ int test_bit(const unsigned* bits, int i) {
    return (bits[i >> 5] >> (i & 31)) & 1u;
}
// floor(a / N) via magic multiply (m = ceil(2^41/N), exact for a*e < 2^41)
__device__ __forceinline__ int mdiv(unsigned a, unsigned long long m) {
    return (int)((a * m) >> MSHIFT);
}

// ---------------------------------------------------------------------------
// Output nodes (last of each graph, batch sorted); init out[] with bias.
// Also verify batch[i] == floor(i*G/N) (magic form) for the formula fast path.
__global__ void k_mark(const int* __restrict__ batch, int N,
                       float* __restrict__ out, const float* __restrict__ b2, int G,
                       unsigned long long m) {
    int i = blockIdx.x * blockDim.x + threadIdx.x;
    if (i < G) out[i] = b2[0];
    if (i >= N) return;
    int bi = batch[i];
    if (bi != mdiv((unsigned)i * (unsigned)G, m))
        d_formula_ok = 0;                       // plain store; any clear wins
    bool last = (i == N - 1) || (bi != batch[i + 1]);
    if (last) {
        atomicOr(&d_isout_bits[i >> 5], 1u << (i & 31));
        atomicOr(&d_need_bits[i >> 5], 1u << (i & 31));
        int s = atomicAdd(&d_nslots, 1);
        if (s < MAXSLOTS) { d_slot[i] = s; d_slotnode[s] = i; }
        int o = atomicAdd(&d_nout, 1);
        if (o < MAXSLOTS) d_outnodes[o] = i;
    }
}

// pass1: deg histogram (RED) + layer-2 edge collect + V1 slot set.
__device__ __forceinline__ void pass1_hit(int sj, int dj) {
    int p = atomicAdd(&d_nl2, 1);
    if (p < MAXL2) d_l2[p] = make_int2(sj, dj);
    unsigned bit = 1u << (sj & 31);
    unsigned old = atomicOr(&d_need_bits[sj >> 5], bit);
    if (!(old & bit)) {
        int s = atomicAdd(&d_nslots, 1);
        if (s < MAXSLOTS) { d_slot[sj] = s; d_slotnode[s] = sj; }
    }
}

// ALU output test: floor((d+1)G/N) != floor(dG/N)  (valid iff formula_ok)
__device__ __forceinline__ int isout_f(int d, int N, unsigned G, unsigned long long m) {
    if (d == N - 1) return 1;
    return mdiv(((unsigned)d + 1u) * G, m) != mdiv((unsigned)d * G, m);
}

__global__ void k_pass1_v4(const int* __restrict__ src, const int4* __restrict__ dst4,
                           int E4, int N, unsigned G, unsigned long long m) {
    int j = blockIdx.x * blockDim.x + threadIdx.x;
    if (j >= E4) return;
    int use_f = d_formula_ok;
    int4 d = __ldg(&dst4[j]);
    atomicAdd(&d_deg[d.x], 1);
    atomicAdd(&d_deg[d.y], 1);
    atomicAdd(&d_deg[d.z], 1);
    atomicAdd(&d_deg[d.w], 1);
    if (use_f) {   // pure-ALU probe: no L1tex wavefront cost
        if (isout_f(d.x, N, G, m)) pass1_hit(__ldg(&src[4 * j + 0]), d.x);
        if (isout_f(d.y, N, G, m)) pass1_hit(__ldg(&src[4 * j + 1]), d.y);
        if (isout_f(d.z, N, G, m)) pass1_hit(__ldg(&src[4 * j + 2]), d.z);
        if (isout_f(d.w, N, G, m)) pass1_hit(__ldg(&src[4 * j + 3]), d.w);
    } else {       // fallback: bitmap probe (L1 hit)
        if (test_bit(d_isout_bits, d.x)) pass1_hit(__ldg(&src[4 * j + 0]), d.x);
        if (test_bit(d_isout_bits, d.y)) pass1_hit(__ldg(&src[4 * j + 1]), d.y);
        if (test_bit(d_isout_bits, d.z)) pass1_hit(__ldg(&src[4 * j + 2]), d.z);
        if (test_bit(d_isout_bits, d.w)) pass1_hit(__ldg(&src[4 * j + 3]), d.w);
    }
}
__global__ void k_pass1_s(const int* __restrict__ src, const int* __restrict__ dst,
                          int E, int N, unsigned G, unsigned long long m) {
    int i = blockIdx.x * blockDim.x + threadIdx.x;
    if (i >= E) return;
    int dj = __ldg(&dst[i]);
    atomicAdd(&d_deg[dj], 1);
    int hit = d_formula_ok ? isout_f(dj, N, G, m) : test_bit(d_isout_bits, dj);
    if (hit) pass1_hit(__ldg(&src[i]), dj);
}

// dinv for all nodes; zero xagg rows for needed nodes
__global__ void k_slots(int N) {
    int i = blockIdx.x * blockDim.x + threadIdx.x;
    if (i >= N) return;
    d_dinv[i] = rsqrtf((float)(d_deg[i] + 1));
    if (test_bit(d_need_bits, i)) {
        int s = d_slot[i];
        if (s < MAXSLOTS) {
            float4* row = (float4*)&d_xagg[(size_t)s * FIN];
            #pragma unroll
            for (int k = 0; k < FIN / 4; k++) row[k] = make_float4(0.f, 0.f, 0.f, 0.f);
        }
    }
}

// scan all edges; edges into needed nodes -> warp-cooperative red.v4 scatter
__global__ void k_gather(const int* __restrict__ src, const int* __restrict__ dst,
                         const float4* __restrict__ x4, int E) {
    int idx  = blockIdx.x * blockDim.x + threadIdx.x;
    int lane = threadIdx.x & 31;
    int s = 0, d = 0, pred = 0;
    if (idx < E) {
        d = __ldg(&dst[idx]);
        pred = test_bit(d_need_bits, d);        // 12.5 KB bitmap: L1 hit
        if (pred) s = __ldg(&src[idx]);
    }
    unsigned mask = __ballot_sync(0xffffffffu, pred);
    while (mask) {
        int b = __ffs(mask) - 1;
        mask &= mask - 1;
        int bs = __shfl_sync(0xffffffffu, s, b);
        int bd = __shfl_sync(0xffffffffu, d, b);
        int sl = d_slot[bd];
        float w = d_dinv[bs];
        float4 xv = __ldg(&x4[(size_t)bs * (FIN / 4) + lane]);
        red_add_v4(&d_xagg[(size_t)sl * FIN + lane * 4],
                   xv.x * w, xv.y * w, xv.z * w, xv.w * w);
    }
}

// per needed node: y = xagg*dinv + x*dinv^2 ; h1 = relu(y@W1+b1) ; t = h1@W2
__global__ void k_compute(const float* __restrict__ x,
                          const float* __restrict__ W1,
                          const float* __restrict__ b1,
                          const float* __restrict__ W2) {
    __shared__ float ysh[FIN];
    __shared__ float redsh[HID];
    int ns = d_nslots; if (ns > MAXSLOTS) ns = MAXSLOTS;
    int t  = threadIdx.x;   // 0..63
    for (int s = blockIdx.x; s < ns; s += gridDim.x) {
        int v = d_slotnode[s];
        float dv  = d_dinv[v];
        float dv2 = dv * dv;
        #pragma unroll
        for (int k = t; k < FIN; k += HID)
            ysh[k] = d_xagg[(size_t)s * FIN + k] * dv + x[(size_t)v * FIN + k] * dv2;
        __syncthreads();
        float acc = 0.f;
        #pragma unroll 16
        for (int k = 0; k < FIN; k++)
            acc = fmaf(ysh[k], W1[k * HID + t], acc);
        float h = fmaxf(acc + b1[t], 0.f);
        redsh[t] = h * W2[t];
        __syncthreads();
        if (t < 32) {
            float p = redsh[t] + redsh[t + 32];
            #pragma unroll
            for (int o = 16; o > 0; o >>= 1)
                p += __shfl_down_sync(0xffffffffu, p, o);
            if (t == 0) d_tval[s] = p;
        }
        __syncthreads();
    }
}

// layer-2 reduce (block 0) + self-loop (block 1) + scratch re-zero (all blocks)
__global__ void k_final(const int* __restrict__ batch, float* __restrict__ out) {
    int i = blockIdx.x * blockDim.x + threadIdx.x;
    if (blockIdx.x == 0) {
        int n1 = d_nl2; if (n1 > MAXL2) n1 = MAXL2;
        for (int k = threadIdx.x; k < n1; k += blockDim.x) {
            int2 e = d_l2[k];
            atomicAdd(&out[batch[e.y]],
                      d_tval[d_slot[e.x]] * d_dinv[e.x] * d_dinv[e.y]);
        }
        __syncthreads();
        if (threadIdx.x == 0) { d_nl2 = 0; }
    } else if (blockIdx.x == 1) {
        int n2 = d_nout; if (n2 > MAXSLOTS) n2 = MAXSLOTS;
        for (int k = threadIdx.x; k < n2; k += blockDim.x) {
            int v  = d_outnodes[k];
            float dv = d_dinv[v];
            atomicAdd(&out[batch[v]], d_tval[d_slot[v]] * dv * dv);
        }
        __syncthreads();
        if (threadIdx.x == 0) { d_nout = 0; d_nslots = 0; d_formula_ok = 1; }
    }
    if (i < MAXN) d_deg[i] = 0;
    if (i < NBW) { d_isout_bits[i] = 0u; d_need_bits[i] = 0u; }
}

// ---------------------------------------------------------------------------
extern "C" void kernel_launch(void* const* d_in, const int* in_sizes, int n_in,
                              void* d_out, int out_size) {
    const float* x     = (const float*)d_in[0];
    const int*   ei    = (const int*)  d_in[1];
    const int*   batch = (const int*)  d_in[2];
    const float* W1    = (const float*)d_in[3];
    const float* b1    = (const float*)d_in[4];
    const float* W2    = (const float*)d_in[5];
    const float* b2    = (const float*)d_in[6];
    float* out = (float*)d_out;

    const int N = in_sizes[2];
    const int E = in_sizes[1] / 2;
    const int G = out_size;

    const int* src = ei;
    const int* dst = ei + E;

    int gN = (N + 255) / 256;
    unsigned long long m = ((1ULL << MSHIFT) + (unsigned)N - 1) / (unsigned)N;

    k_mark<<<gN, 256>>>(batch, N, out, b2, G, m);

    bool vec_ok = ((E & 3) == 0) &&
                  ((((uintptr_t)src) & 15) == 0) && ((((uintptr_t)dst) & 15) == 0);
    if (vec_ok) {
        int E4 = E / 4;
        k_pass1_v4<<<(E4 + 255) / 256, 256>>>(src, (const int4*)dst, E4, N, (unsigned)G, m);
    } else {
        k_pass1_s<<<(E + 255) / 256, 256>>>(src, dst, E, N, (unsigned)G, m);
    }

    k_slots  <<<gN, 256>>>(N);
    k_gather <<<(E + 255) / 256, 256>>>(src, dst, (const float4*)x, E);
    k_compute<<<2048, HID>>>(x, W1, b1, W2);
    k_final  <<<gN, 256>>>(batch, out);
}